// round 11
// baseline (speedup 1.0000x reference)
#include <cuda_runtime.h>
#include <cuda_bf16.h>

// EquiConv fused kernel: GEMM-restructured, 4 edges/warp, packed f32x2 FMA,
// TMA double-buffered weight staging, A-factored ss contraction, mbarrier pipeline.
// E=20000, S=64, V=32, FC_IN=128, HID=64. out (E,160).

#define TE 32      // edges per block (20000/32 = 625 blocks exactly)
#define NT 256
#define KC 16      // K chunk
#define NC 320     // total chunks: 256 ss + 64 vv

#define INV_SQRT3_F 0.5773502691896258f
#define A_SC_F 0.013975424859373686f   // 1/sqrt(64*64+32*32)
#define A_VEC_F 0.015625f              // 1/sqrt(2*64*32)

// shared layout (floats)
#define OFF_X1ST 0                 // [64][36]  transposed x1s
#define OFF_X2ST 2304              // [64][36]
#define OFF_X1V  4608              // [32][97]
#define OFF_X2V  7712              // [32][97]
#define OFF_WOUT 10816             // [32][96]
#define OFF_SIG  13888             // [32][32]
#define OFF_UN   14912             // 4096 union:
                                   //   MLP: fw 2048 + h2 1024
                                   //   main: WBUF 2x1536 (=3072) + Pc 2x512 (=1024)
                                   //   vec: 4096 weight chunk
#define OFF_MBAR 19008             // 4 mbarriers (8 floats)
#define SMEM_FLOATS 19024          // 76096 bytes (x3 blocks = 223 KiB/SM)

typedef unsigned long long u64t;

__device__ __forceinline__ float sigmoidf_(float x) {
    return __fdividef(1.0f, 1.0f + __expf(-x));
}
__device__ __forceinline__ u64t splat2(float w) {
    u64t r;
    unsigned int wi = __float_as_uint(w);
    asm("mov.b64 %0, {%1, %1};" : "=l"(r) : "r"(wi));
    return r;
}
__device__ __forceinline__ void fma2(u64t& d, u64t a, u64t b) {
    asm("fma.rn.f32x2 %0, %1, %2, %0;" : "+l"(d) : "l"(a), "l"(b));
}
__device__ __forceinline__ float2 unpack2(u64t v) {
    unsigned int lo, hi;
    asm("mov.b64 {%0, %1}, %2;" : "=r"(lo), "=r"(hi) : "l"(v));
    float2 f;
    f.x = __uint_as_float(lo);
    f.y = __uint_as_float(hi);
    return f;
}
__device__ __forceinline__ unsigned smem_u32(const void* p) {
    return (unsigned)__cvta_generic_to_shared(p);
}
__device__ __forceinline__ void mbar_init(unsigned a, unsigned cnt) {
    asm volatile("mbarrier.init.shared.b64 [%0], %1;" :: "r"(a), "r"(cnt) : "memory");
}
__device__ __forceinline__ void mbar_expect_tx(unsigned a, unsigned bytes) {
    asm volatile("mbarrier.arrive.expect_tx.shared.b64 _, [%0], %1;" :: "r"(a), "r"(bytes) : "memory");
}
__device__ __forceinline__ void mbar_arrive(unsigned a) {
    asm volatile("mbarrier.arrive.shared.b64 _, [%0];" :: "r"(a) : "memory");
}
__device__ __forceinline__ void mbar_wait(unsigned a, unsigned ph) {
    asm volatile(
        "{\n\t"
        ".reg .pred P1;\n\t"
        "WAIT_LOOP_%=:\n\t"
        "mbarrier.try_wait.parity.acquire.cta.shared::cta.b64 P1, [%0], %1, 0x989680;\n\t"
        "@P1 bra.uni WAIT_DONE_%=;\n\t"
        "bra.uni WAIT_LOOP_%=;\n\t"
        "WAIT_DONE_%=:\n\t"
        "}"
        :: "r"(a), "r"(ph) : "memory");
}
__device__ __forceinline__ void tma_bulk_g2s(unsigned dst, const void* src,
                                             unsigned bytes, unsigned mbar) {
    asm volatile(
        "cp.async.bulk.shared::cta.global.mbarrier::complete_tx::bytes [%0], [%1], %2, [%3];"
        :: "r"(dst), "l"(src), "r"(bytes), "r"(mbar) : "memory");
}

__global__ __launch_bounds__(NT, 3) void equiconv_kernel(
    const float* __restrict__ fea_in1,
    const float* __restrict__ fea_in2,
    const float* __restrict__ fea_weight,
    const float* __restrict__ wsss,   // (64,64,64)  k*64 + w   (k = u*64+v)
    const float* __restrict__ wvvs,   // (32,32,64)
    const float* __restrict__ wssg,   // (64,64,32)
    const float* __restrict__ wvvg,   // (32,32,32)
    const float* __restrict__ wsvv,   // (64,32,32)  u*1024 + v*32 + w
    const float* __restrict__ wvsv,   // (32,64,32)  u*2048 + v*32 + w
    const float* __restrict__ fw1, const float* __restrict__ fb1,
    const float* __restrict__ fw2, const float* __restrict__ fb2,
    const float* __restrict__ fw3, const float* __restrict__ fb3,
    float* __restrict__ out)
{
    extern __shared__ float smem[];
    float* s_x1sT = smem + OFF_X1ST;
    float* s_x2sT = smem + OFF_X2ST;
    float* s_x1v  = smem + OFF_X1V;
    float* s_x2v  = smem + OFF_X2V;
    float* s_wout = smem + OFF_WOUT;
    float* s_sig  = smem + OFF_SIG;
    float* s_un   = smem + OFF_UN;
    float* s_wbuf = s_un;              // 2 x 1536 floats: [16][64] WS + [16][32] WG
    float* s_pc   = s_un + 3072;       // 2 x 512 floats (vv P chunks)

    const int tid  = threadIdx.x;
    const int wid  = tid >> 5;
    const int lane = tid & 31;
    const int e4   = 4 * wid;          // warp owns edges e4..e4+3
    const int e0g  = blockIdx.x * TE;

    const unsigned mb_full0  = smem_u32(smem + OFF_MBAR);
    const unsigned mb_full1  = mb_full0 + 8;
    const unsigned mb_empty0 = mb_full0 + 16;
    const unsigned mb_empty1 = mb_full0 + 24;
    const unsigned wbuf_a    = smem_u32(s_wbuf);

    if (tid == 0) {
        mbar_init(mb_full0, 1);
        mbar_init(mb_full1, 1);
        mbar_init(mb_empty0, 256);
        mbar_init(mb_empty1, 256);
    }

    // ---- stage edge features (scalars transposed) ----
    for (int idx = tid; idx < TE * 160; idx += NT) {
        int e = idx / 160;
        int c = idx - e * 160;
        float v1 = fea_in1[e0g * 160 + idx];
        float v2 = fea_in2[e0g * 160 + idx];
        if (c < 64) { s_x1sT[c * 36 + e] = v1; s_x2sT[c * 36 + e] = v2; }
        else        { s_x1v[e * 97 + (c - 64)] = v1; s_x2v[e * 97 + (c - 64)] = v2; }
    }

    // ---- MLP in 2 passes of 16 edges (union buffer: fw @0, h2 @2048, h1 in s_sig) ----
    for (int p = 0; p < 2; p++) {
        const int eb0 = p * 16;
        __syncthreads();
        for (int idx = tid; idx < 16 * 128; idx += NT)
            s_un[idx] = fea_weight[(e0g + eb0) * 128 + idx];
        __syncthreads();
        #pragma unroll
        for (int it = 0; it < 4; it++) {
            int o = tid + NT * it; int e = o >> 6, j = o & 63;
            float acc = fb1[j];
            const float* xe = s_un + e * 128;
            #pragma unroll 8
            for (int k = 0; k < 128; k++) acc += xe[k] * fw1[k * 64 + j];
            s_sig[o] = acc * sigmoidf_(acc);
        }
        __syncthreads();
        #pragma unroll
        for (int it = 0; it < 4; it++) {
            int o = tid + NT * it; int e = o >> 6, j = o & 63;
            float acc = fb2[j];
            const float* xe = s_sig + e * 64;
            #pragma unroll 8
            for (int k = 0; k < 64; k++) acc += xe[k] * fw2[k * 64 + j];
            s_un[2048 + o] = acc * sigmoidf_(acc);
        }
        __syncthreads();
        #pragma unroll
        for (int it = 0; it < 6; it++) {
            int o = tid + NT * it; int e = o / 96, j = o - e * 96;
            float acc = fb3[j];
            const float* xe = s_un + 2048 + e * 64;
            #pragma unroll 8
            for (int k = 0; k < 64; k++) acc += xe[k] * fw3[k * 96 + j];
            s_wout[(eb0 + e) * 96 + j] = acc;
        }
    }
    __syncthreads();   // MLP scratch dead; WBUF region free; mbar init visible

    // ---- prologue: issue W chunks 0 and 1 via TMA ----
    if (tid == 0) {
        #pragma unroll
        for (int cj = 0; cj < 2; cj++) {
            int k0 = cj * KC;
            unsigned mb = cj ? mb_full1 : mb_full0;
            mbar_expect_tx(mb, 6144);
            tma_bulk_g2s(wbuf_a + cj * 1536 * 4, wsss + k0 * 64, 4096, mb);
            tma_bulk_g2s(wbuf_a + cj * 1536 * 4 + 4096, wssg + k0 * 32, 2048, mb);
        }
    }

    // ---- main GEMM: [sc|g] = P @ Wcat, K = 5120 in 320 chunks of 16 ----
    u64t accP[2][3] = {{0ull, 0ull, 0ull}, {0ull, 0ull, 0ull}};

    for (int ci = 0; ci < NC; ci++) {
        const int b = ci & 1;
        const unsigned ph = (ci >> 1) & 1;
        const unsigned mbF = b ? mb_full1 : mb_full0;
        const unsigned mbE = b ? mb_empty1 : mb_empty0;

        if (ci >= 256) {
            // stage Pc (double-buffered) for this vv chunk; depends only on x
            const int u  = (ci - 256) >> 1;
            const int v0 = ((ci - 256) & 1) * KC;
            #pragma unroll
            for (int i = 0; i < 2; i++) {
                int idx = tid + NT * i;
                int kk = idx >> 5, e = idx & 31;
                const float* av = s_x1v + e * 97 + u * 3;
                const float* bv = s_x2v + e * 97 + (v0 + kk) * 3;
                s_pc[b * 512 + kk * 32 + e] =
                    INV_SQRT3_F * (av[0] * bv[0] + av[1] * bv[1] + av[2] * bv[2]);
            }
            __syncthreads();
        }

        mbar_wait(mbF, ph);
        const float* WS = s_wbuf + b * 1536;        // [16][64]
        const float* WG = WS + 1024;                // [16][32]

        if (ci < 256) {
            // ss region: u fixed per chunk -> factor x1s[u] out of the kk-sum
            const int u  = ci >> 2;
            const int v0 = (ci & 3) * KC;
            const float* xp = s_x2sT + v0 * 36 + e4;
            u64t p00 = 0ull, p01 = 0ull, p02 = 0ull;
            u64t p10 = 0ull, p11 = 0ull, p12 = 0ull;
            #pragma unroll
            for (int kk = 0; kk < KC; kk++) {
                ulonglong2 xq = *(const ulonglong2*)(xp + kk * 36);  // 4 edges bcast
                u64t w0 = splat2(WS[kk * 64 + lane]);
                u64t w1 = splat2(WS[kk * 64 + 32 + lane]);
                u64t w2 = splat2(WG[kk * 32 + lane]);
                fma2(p00, xq.x, w0); fma2(p01, xq.x, w1); fma2(p02, xq.x, w2);
                fma2(p10, xq.y, w0); fma2(p11, xq.y, w1); fma2(p12, xq.y, w2);
            }
            ulonglong2 Aq = *(const ulonglong2*)(s_x1sT + u * 36 + e4);
            fma2(accP[0][0], p00, Aq.x);
            fma2(accP[0][1], p01, Aq.x);
            fma2(accP[0][2], p02, Aq.x);
            fma2(accP[1][0], p10, Aq.y);
            fma2(accP[1][1], p11, Aq.y);
            fma2(accP[1][2], p12, Aq.y);
        } else {
            const float* pp = s_pc + b * 512 + e4;
            #pragma unroll
            for (int kk = 0; kk < KC; kk++) {
                ulonglong2 pq = *(const ulonglong2*)(pp + kk * 32);
                u64t w0 = splat2(WS[kk * 64 + lane]);
                u64t w1 = splat2(WS[kk * 64 + 32 + lane]);
                u64t w2 = splat2(WG[kk * 32 + lane]);
                fma2(accP[0][0], pq.x, w0);
                fma2(accP[0][1], pq.x, w1);
                fma2(accP[0][2], pq.x, w2);
                fma2(accP[1][0], pq.y, w0);
                fma2(accP[1][1], pq.y, w1);
                fma2(accP[1][2], pq.y, w2);
            }
        }

        mbar_arrive(mbE);
        if (tid == 0 && ci + 2 < NC) {
            mbar_wait(mbE, ph);              // all consumers done with buffer b
            const int cj = ci + 2;
            const float* srcS;
            const float* srcG;
            if (cj < 256) { int k0 = cj * KC; srcS = wsss + k0 * 64; srcG = wssg + k0 * 32; }
            else          { int k2 = (cj - 256) * KC; srcS = wvvs + k2 * 64; srcG = wvvg + k2 * 32; }
            mbar_expect_tx(mbF, 6144);
            tma_bulk_g2s(wbuf_a + b * 1536 * 4, srcS, 4096, mbF);
            tma_bulk_g2s(wbuf_a + b * 1536 * 4 + 4096, srcG, 2048, mbF);
        }
    }

    // ---- sc/g epilogue ----
    #pragma unroll
    for (int pr = 0; pr < 2; pr++) {
        float2 c0 = unpack2(accP[pr][0]);
        float2 c1 = unpack2(accP[pr][1]);
        float2 c2 = unpack2(accP[pr][2]);
        #pragma unroll
        for (int h = 0; h < 2; h++) {
            int e = e4 + 2 * pr + h;
            long base = (long)(e0g + e) * 160;
            float a0 = h ? c0.y : c0.x;
            float a1 = h ? c1.y : c1.x;
            float a2 = h ? c2.y : c2.x;
            float s;
            s = A_SC_F * a0;
            out[base + lane] = s * sigmoidf_(s) * s_wout[e * 96 + lane];
            s = A_SC_F * a1;
            out[base + lane + 32] = s * sigmoidf_(s) * s_wout[e * 96 + lane + 32];
            s_sig[e * 32 + lane] = sigmoidf_(A_SC_F * a2);
        }
    }

    // ---- vec: factored GEMMs, 4 edges/warp, packed f32x2 ----
    float vA[4][3];
    #pragma unroll
    for (int j = 0; j < 4; j++)
        #pragma unroll
        for (int c = 0; c < 3; c++) vA[j][c] = 0.f;

    // sv:  B1[e,v,w] = sum_u x1s[e,u]*wsvv[u,v,w];  vec += B1 * x2v[e,v,i]
    for (int vc = 0; vc < 16; vc++) {
        __syncthreads();
        int v0 = vc * 2;
        #pragma unroll
        for (int i = 0; i < 4; i++) {
            int fidx = tid + NT * i;      // [128 rows][32]: row = u*2 + vv
            int r = fidx >> 3, c4 = fidx & 7;
            int u = r >> 1, vv = r & 1;
            *(float4*)(s_un + r * 32 + c4 * 4) =
                *(const float4*)(wsvv + u * 1024 + (v0 + vv) * 32 + c4 * 4);
        }
        __syncthreads();
        u64t b0p[2] = {0ull, 0ull};
        u64t b1p[2] = {0ull, 0ull};
        const float* wv = s_un + lane;
        #pragma unroll 8
        for (int u = 0; u < 64; u++) {
            ulonglong2 x = *(const ulonglong2*)(s_x1sT + u * 36 + e4);
            u64t w0 = splat2(wv[(u * 2 + 0) * 32]);
            u64t w1 = splat2(wv[(u * 2 + 1) * 32]);
            fma2(b0p[0], x.x, w0); fma2(b0p[1], x.y, w0);
            fma2(b1p[0], x.x, w1); fma2(b1p[1], x.y, w1);
        }
        float2 b0a = unpack2(b0p[0]), b0b = unpack2(b0p[1]);
        float2 b1a = unpack2(b1p[0]), b1b = unpack2(b1p[1]);
        float b0[4] = {b0a.x, b0a.y, b0b.x, b0b.y};
        float b1[4] = {b1a.x, b1a.y, b1b.x, b1b.y};
        #pragma unroll
        for (int j = 0; j < 4; j++) {
            const float* xv = s_x2v + (e4 + j) * 97 + v0 * 3;
            vA[j][0] += b0[j] * xv[0] + b1[j] * xv[3];
            vA[j][1] += b0[j] * xv[1] + b1[j] * xv[4];
            vA[j][2] += b0[j] * xv[2] + b1[j] * xv[5];
        }
    }

    // vs:  B2[e,u,w] = sum_v x2s[e,v]*wvsv[u,v,w];  vec += B2 * x1v[e,u,i]
    for (int uc = 0; uc < 16; uc++) {
        __syncthreads();
        int u0 = uc * 2;
        #pragma unroll
        for (int i = 0; i < 4; i++) {
            int fidx = tid + NT * i;      // [128 rows][32]: row = uu*64 + v
            int r = fidx >> 3, c4 = fidx & 7;
            int uu = r >> 6, v = r & 63;
            *(float4*)(s_un + r * 32 + c4 * 4) =
                *(const float4*)(wvsv + (u0 + uu) * 2048 + v * 32 + c4 * 4);
        }
        __syncthreads();
        u64t b0p[2] = {0ull, 0ull};
        u64t b1p[2] = {0ull, 0ull};
        const float* wv = s_un + lane;
        #pragma unroll 8
        for (int v = 0; v < 64; v++) {
            ulonglong2 x = *(const ulonglong2*)(s_x2sT + v * 36 + e4);
            u64t w0 = splat2(wv[v * 32]);
            u64t w1 = splat2(wv[(64 + v) * 32]);
            fma2(b0p[0], x.x, w0); fma2(b0p[1], x.y, w0);
            fma2(b1p[0], x.x, w1); fma2(b1p[1], x.y, w1);
        }
        float2 b0a = unpack2(b0p[0]), b0b = unpack2(b0p[1]);
        float2 b1a = unpack2(b1p[0]), b1b = unpack2(b1p[1]);
        float b0[4] = {b0a.x, b0a.y, b0b.x, b0b.y};
        float b1[4] = {b1a.x, b1a.y, b1b.x, b1b.y};
        #pragma unroll
        for (int j = 0; j < 4; j++) {
            const float* xv = s_x1v + (e4 + j) * 97 + u0 * 3;
            vA[j][0] += b0[j] * xv[0] + b1[j] * xv[3];
            vA[j][1] += b0[j] * xv[1] + b1[j] * xv[4];
            vA[j][2] += b0[j] * xv[2] + b1[j] * xv[5];
        }
    }

    // ---- vec epilogue ----
    #pragma unroll
    for (int j = 0; j < 4; j++) {
        int e = e4 + j;
        float m = A_VEC_F * s_sig[e * 32 + lane] * s_wout[e * 96 + 64 + lane];
        float* o = out + (long)(e0g + e) * 160 + 64 + lane * 3;
        o[0] = vA[j][0] * m;
        o[1] = vA[j][1] * m;
        o[2] = vA[j][2] * m;
    }
}

extern "C" void kernel_launch(void* const* d_in, const int* in_sizes, int n_in,
                              void* d_out, int out_size) {
    (void)in_sizes; (void)n_in; (void)out_size;
    const float* fea_in1    = (const float*)d_in[0];
    const float* fea_in2    = (const float*)d_in[1];
    const float* fea_weight = (const float*)d_in[2];
    const float* w_ss_s     = (const float*)d_in[3];
    const float* w_vv_s     = (const float*)d_in[4];
    const float* w_ss_g     = (const float*)d_in[5];
    const float* w_vv_g     = (const float*)d_in[6];
    const float* w_sv_v     = (const float*)d_in[7];
    const float* w_vs_v     = (const float*)d_in[8];
    const float* fc_w1      = (const float*)d_in[9];
    const float* fc_b1      = (const float*)d_in[10];
    const float* fc_w2      = (const float*)d_in[11];
    const float* fc_b2      = (const float*)d_in[12];
    const float* fc_w3      = (const float*)d_in[13];
    const float* fc_b3      = (const float*)d_in[14];
    float* out = (float*)d_out;

    cudaFuncSetAttribute(equiconv_kernel,
                         cudaFuncAttributeMaxDynamicSharedMemorySize,
                         SMEM_FLOATS * sizeof(float));
    cudaFuncSetAttribute(equiconv_kernel,
                         cudaFuncAttributePreferredSharedMemoryCarveout,
                         cudaSharedmemCarveoutMaxShared);

    const int E = 20000;
    dim3 grid(E / TE);
    dim3 block(NT);
    equiconv_kernel<<<grid, block, SMEM_FLOATS * sizeof(float)>>>(
        fea_in1, fea_in2, fea_weight,
        w_ss_s, w_vv_s, w_ss_g, w_vv_g, w_sv_v, w_vs_v,
        fc_w1, fc_b1, fc_w2, fc_b2, fc_w3, fc_b3,
        out);
}

// round 12
// speedup vs baseline: 1.1808x; 1.1808x over previous
#include <cuda_runtime.h>
#include <cuda_bf16.h>

// EquiConv fused kernel: 8 edges/warp (NT=128), A-factored ss contraction,
// register-prefetched weight staging, packed f32x2 FMA throughout.
// E=20000, S=64, V=32, FC_IN=128, HID=64. out (E,160).

#define TE 32      // edges per block (20000/32 = 625 blocks exactly)
#define NT 128     // 4 warps; each warp owns 8 edges
#define KC 32      // K chunk
#define NCH 160    // chunks: 128 ss + 32 vv

#define INV_SQRT3_F 0.5773502691896258f
#define A_SC_F 0.013975424859373686f   // 1/sqrt(64*64+32*32)
#define A_VEC_F 0.015625f              // 1/sqrt(2*64*32)

// shared layout (floats)
#define OFF_X1ST 0                 // [64][36]  transposed x1s
#define OFF_X2ST 2304              // [64][36]
#define OFF_X1V  4608              // [32][97]
#define OFF_X2V  7712              // [32][97]
#define OFF_WOUT 10816             // [32][96]
#define OFF_SIG  13888             // [32][32]
#define OFF_UN   14912             // 4096 union: {MLP fw/h2} / {Wc 3072 + Pc 1024} / {vec 4096}
#define SMEM_FLOATS 19008          // 76032 bytes (x3 blocks/SM)

typedef unsigned long long u64t;

__device__ __forceinline__ float sigmoidf_(float x) {
    return __fdividef(1.0f, 1.0f + __expf(-x));
}
__device__ __forceinline__ u64t splat2(float w) {
    u64t r;
    unsigned int wi = __float_as_uint(w);
    asm("mov.b64 %0, {%1, %1};" : "=l"(r) : "r"(wi));
    return r;
}
__device__ __forceinline__ void fma2(u64t& d, u64t a, u64t b) {
    asm("fma.rn.f32x2 %0, %1, %2, %0;" : "+l"(d) : "l"(a), "l"(b));
}
__device__ __forceinline__ float2 unpack2(u64t v) {
    unsigned int lo, hi;
    asm("mov.b64 {%0, %1}, %2;" : "=r"(lo), "=r"(hi) : "l"(v));
    float2 f;
    f.x = __uint_as_float(lo);
    f.y = __uint_as_float(hi);
    return f;
}

__global__ __launch_bounds__(NT, 3) void equiconv_kernel(
    const float* __restrict__ fea_in1,
    const float* __restrict__ fea_in2,
    const float* __restrict__ fea_weight,
    const float* __restrict__ wsss,   // (64,64,64)  k*64 + w   (k = u*64+v)
    const float* __restrict__ wvvs,   // (32,32,64)
    const float* __restrict__ wssg,   // (64,64,32)
    const float* __restrict__ wvvg,   // (32,32,32)
    const float* __restrict__ wsvv,   // (64,32,32)  u*1024 + v*32 + w
    const float* __restrict__ wvsv,   // (32,64,32)  u*2048 + v*32 + w
    const float* __restrict__ fw1, const float* __restrict__ fb1,
    const float* __restrict__ fw2, const float* __restrict__ fb2,
    const float* __restrict__ fw3, const float* __restrict__ fb3,
    float* __restrict__ out)
{
    extern __shared__ float smem[];
    float* s_x1sT = smem + OFF_X1ST;
    float* s_x2sT = smem + OFF_X2ST;
    float* s_x1v  = smem + OFF_X1V;
    float* s_x2v  = smem + OFF_X2V;
    float* s_wout = smem + OFF_WOUT;
    float* s_sig  = smem + OFF_SIG;
    float* s_un   = smem + OFF_UN;
    float* Wc     = s_un;              // [32][96] = 3072
    float* s_pc   = s_un + 3072;       // [32][32] = 1024 (vv P chunk)

    const int tid  = threadIdx.x;
    const int wid  = tid >> 5;         // 0..3
    const int lane = tid & 31;
    const int e8   = 8 * wid;          // warp owns edges e8..e8+7
    const int e0g  = blockIdx.x * TE;

    // ---- stage edge features (scalars transposed) ----
    for (int idx = tid; idx < TE * 160; idx += NT) {
        int e = idx / 160;
        int c = idx - e * 160;
        float v1 = fea_in1[e0g * 160 + idx];
        float v2 = fea_in2[e0g * 160 + idx];
        if (c < 64) { s_x1sT[c * 36 + e] = v1; s_x2sT[c * 36 + e] = v2; }
        else        { s_x1v[e * 97 + (c - 64)] = v1; s_x2v[e * 97 + (c - 64)] = v2; }
    }

    // ---- MLP in 2 passes of 16 edges (fw @un[0], h1 in s_sig, h2 @un[2048]) ----
    for (int p = 0; p < 2; p++) {
        const int eb0 = p * 16;
        __syncthreads();
        for (int idx = tid; idx < 16 * 128; idx += NT)
            s_un[idx] = fea_weight[(e0g + eb0) * 128 + idx];
        __syncthreads();
        for (int o = tid; o < 16 * 64; o += NT) {
            int e = o >> 6, j = o & 63;
            float acc = fb1[j];
            const float* xe = s_un + e * 128;
            #pragma unroll 8
            for (int k = 0; k < 128; k++) acc += xe[k] * fw1[k * 64 + j];
            s_sig[o] = acc * sigmoidf_(acc);
        }
        __syncthreads();
        for (int o = tid; o < 16 * 64; o += NT) {
            int e = o >> 6, j = o & 63;
            float acc = fb2[j];
            const float* xe = s_sig + e * 64;
            #pragma unroll 8
            for (int k = 0; k < 64; k++) acc += xe[k] * fw2[k * 64 + j];
            s_un[2048 + o] = acc * sigmoidf_(acc);
        }
        __syncthreads();
        for (int o = tid; o < 16 * 96; o += NT) {
            int e = o / 96, j = o - e * 96;
            float acc = fb3[j];
            const float* xe = s_un + 2048 + e * 64;
            #pragma unroll 8
            for (int k = 0; k < 64; k++) acc += xe[k] * fw3[k * 96 + j];
            s_wout[(eb0 + e) * 96 + j] = acc;
        }
    }

    // ---- main GEMM: [sc|g](e,0:96) over K=5120, 160 chunks of 32 ----
    // accP[pr][col]: pr = edge pair (e8+2pr, e8+2pr+1); col = {lane, lane+32, g lane}
    u64t accP[4][3];
    #pragma unroll
    for (int pr = 0; pr < 4; pr++)
        #pragma unroll
        for (int c = 0; c < 3; c++) accP[pr][c] = 0ull;

    // prefetch W chunk 0 into registers
    float4 wsreg[4], wgreg[2];
    {
        const float* srcS = wsss;
        const float* srcG = wssg;
        #pragma unroll
        for (int i = 0; i < 4; i++) {
            int idx = tid + NT * i; int row = idx >> 4, c4 = idx & 15;
            wsreg[i] = *(const float4*)(srcS + row * 64 + c4 * 4);
        }
        #pragma unroll
        for (int i = 0; i < 2; i++) {
            int idx = tid + NT * i; int row = idx >> 3, c4 = idx & 7;
            wgreg[i] = *(const float4*)(srcG + row * 32 + c4 * 4);
        }
    }

    for (int ci = 0; ci < NCH; ci++) {
        __syncthreads();   // prior chunk's consumers done with Wc / s_pc
        // store current chunk's W
        #pragma unroll
        for (int i = 0; i < 4; i++) {
            int idx = tid + NT * i; int row = idx >> 4, c4 = idx & 15;
            *(float4*)(Wc + row * 96 + c4 * 4) = wsreg[i];
        }
        #pragma unroll
        for (int i = 0; i < 2; i++) {
            int idx = tid + NT * i; int row = idx >> 3, c4 = idx & 7;
            *(float4*)(Wc + row * 96 + 64 + c4 * 4) = wgreg[i];
        }
        // prefetch next chunk's W (lands during compute below)
        if (ci + 1 < NCH) {
            const int cj = ci + 1;
            const float* nS = (cj < 128) ? (wsss + cj * 2048) : (wvvs + (cj - 128) * 2048);
            const float* nG = (cj < 128) ? (wssg + cj * 1024) : (wvvg + (cj - 128) * 1024);
            #pragma unroll
            for (int i = 0; i < 4; i++) {
                int idx = tid + NT * i; int row = idx >> 4, c4 = idx & 15;
                wsreg[i] = *(const float4*)(nS + row * 64 + c4 * 4);
            }
            #pragma unroll
            for (int i = 0; i < 2; i++) {
                int idx = tid + NT * i; int row = idx >> 3, c4 = idx & 7;
                wgreg[i] = *(const float4*)(nG + row * 32 + c4 * 4);
            }
        }
        // vv region: stage P chunk (u fixed = ci-128, kk = v)
        if (ci >= 128) {
            const int u = ci - 128;
            #pragma unroll
            for (int i = 0; i < 8; i++) {
                int idx = tid + NT * i;
                int kk = idx >> 5, e = idx & 31;
                const float* av = s_x1v + e * 97 + u * 3;
                const float* bv = s_x2v + e * 97 + kk * 3;
                s_pc[kk * 32 + e] =
                    INV_SQRT3_F * (av[0] * bv[0] + av[1] * bv[1] + av[2] * bv[2]);
            }
        }
        __syncthreads();

        if (ci < 128) {
            // ss: u fixed per chunk -> factor x1s[u] out of the kk-sum
            const int u  = ci >> 1;
            const int v0 = (ci & 1) * KC;
            const float* xp = s_x2sT + v0 * 36 + e8;
            u64t p[4][3];
            #pragma unroll
            for (int pr = 0; pr < 4; pr++)
                #pragma unroll
                for (int c = 0; c < 3; c++) p[pr][c] = 0ull;
            #pragma unroll 8
            for (int kk = 0; kk < KC; kk++) {
                ulonglong2 x0 = *(const ulonglong2*)(xp + kk * 36);       // edges e8..e8+3
                ulonglong2 x1 = *(const ulonglong2*)(xp + kk * 36 + 4);   // edges e8+4..e8+7
                u64t w0 = splat2(Wc[kk * 96 + lane]);
                u64t w1 = splat2(Wc[kk * 96 + 32 + lane]);
                u64t w2 = splat2(Wc[kk * 96 + 64 + lane]);
                fma2(p[0][0], x0.x, w0); fma2(p[0][1], x0.x, w1); fma2(p[0][2], x0.x, w2);
                fma2(p[1][0], x0.y, w0); fma2(p[1][1], x0.y, w1); fma2(p[1][2], x0.y, w2);
                fma2(p[2][0], x1.x, w0); fma2(p[2][1], x1.x, w1); fma2(p[2][2], x1.x, w2);
                fma2(p[3][0], x1.y, w0); fma2(p[3][1], x1.y, w1); fma2(p[3][2], x1.y, w2);
            }
            ulonglong2 A0 = *(const ulonglong2*)(s_x1sT + u * 36 + e8);
            ulonglong2 A1 = *(const ulonglong2*)(s_x1sT + u * 36 + e8 + 4);
            #pragma unroll
            for (int c = 0; c < 3; c++) {
                fma2(accP[0][c], p[0][c], A0.x);
                fma2(accP[1][c], p[1][c], A0.y);
                fma2(accP[2][c], p[2][c], A1.x);
                fma2(accP[3][c], p[3][c], A1.y);
            }
        } else {
            const float* pp = s_pc + e8;
            #pragma unroll 8
            for (int kk = 0; kk < KC; kk++) {
                ulonglong2 x0 = *(const ulonglong2*)(pp + kk * 32);
                ulonglong2 x1 = *(const ulonglong2*)(pp + kk * 32 + 4);
                u64t w0 = splat2(Wc[kk * 96 + lane]);
                u64t w1 = splat2(Wc[kk * 96 + 32 + lane]);
                u64t w2 = splat2(Wc[kk * 96 + 64 + lane]);
                fma2(accP[0][0], x0.x, w0); fma2(accP[0][1], x0.x, w1); fma2(accP[0][2], x0.x, w2);
                fma2(accP[1][0], x0.y, w0); fma2(accP[1][1], x0.y, w1); fma2(accP[1][2], x0.y, w2);
                fma2(accP[2][0], x1.x, w0); fma2(accP[2][1], x1.x, w1); fma2(accP[2][2], x1.x, w2);
                fma2(accP[3][0], x1.y, w0); fma2(accP[3][1], x1.y, w1); fma2(accP[3][2], x1.y, w2);
            }
        }
    }

    // ---- sc/g epilogue ----
    #pragma unroll
    for (int pr = 0; pr < 4; pr++) {
        float2 c0 = unpack2(accP[pr][0]);
        float2 c1 = unpack2(accP[pr][1]);
        float2 c2 = unpack2(accP[pr][2]);
        #pragma unroll
        for (int h = 0; h < 2; h++) {
            int e = e8 + 2 * pr + h;
            long base = (long)(e0g + e) * 160;
            float a0 = h ? c0.y : c0.x;
            float a1 = h ? c1.y : c1.x;
            float a2 = h ? c2.y : c2.x;
            float s;
            s = A_SC_F * a0;
            out[base + lane] = s * sigmoidf_(s) * s_wout[e * 96 + lane];
            s = A_SC_F * a1;
            out[base + lane + 32] = s * sigmoidf_(s) * s_wout[e * 96 + lane + 32];
            s_sig[e * 32 + lane] = sigmoidf_(A_SC_F * a2);
        }
    }

    // ---- vec: factored GEMMs, 8 edges/warp, register-prefetched staging ----
    float vA[8][3];
    #pragma unroll
    for (int j = 0; j < 8; j++)
        #pragma unroll
        for (int c = 0; c < 3; c++) vA[j][c] = 0.f;

    float4 vreg[8];
    // prefetch sv chunk 0: rows r = u*2+vv -> wsvv[u][v0+vv][.]
    #pragma unroll
    for (int i = 0; i < 8; i++) {
        int idx = tid + NT * i; int r = idx >> 3, c4 = idx & 7;
        vreg[i] = *(const float4*)(wsvv + (r >> 1) * 1024 + (r & 1) * 32 + c4 * 4);
    }

    // sv:  B1[e,v,w] = sum_u x1s[e,u]*wsvv[u,v,w];  vec += B1 * x2v[e,v,i]
    for (int vc = 0; vc < 16; vc++) {
        __syncthreads();
        #pragma unroll
        for (int i = 0; i < 8; i++) {
            int idx = tid + NT * i; int r = idx >> 3, c4 = idx & 7;
            *(float4*)(s_un + r * 32 + c4 * 4) = vreg[i];
        }
        // prefetch next sv chunk, or first vs chunk
        if (vc + 1 < 16) {
            int v0 = (vc + 1) * 2;
            #pragma unroll
            for (int i = 0; i < 8; i++) {
                int idx = tid + NT * i; int r = idx >> 3, c4 = idx & 7;
                vreg[i] = *(const float4*)(wsvv + (r >> 1) * 1024 + (v0 + (r & 1)) * 32 + c4 * 4);
            }
        } else {
            #pragma unroll
            for (int i = 0; i < 8; i++) {
                int idx = tid + NT * i; int r = idx >> 3, c4 = idx & 7;
                vreg[i] = *(const float4*)(wvsv + (r >> 6) * 2048 + (r & 63) * 32 + c4 * 4);
            }
        }
        __syncthreads();

        int v0 = vc * 2;
        u64t b0p[4] = {0ull, 0ull, 0ull, 0ull};
        u64t b1p[4] = {0ull, 0ull, 0ull, 0ull};
        const float* wv = s_un + lane;
        #pragma unroll 8
        for (int u = 0; u < 64; u++) {
            ulonglong2 x0 = *(const ulonglong2*)(s_x1sT + u * 36 + e8);
            ulonglong2 x1 = *(const ulonglong2*)(s_x1sT + u * 36 + e8 + 4);
            u64t w0 = splat2(wv[(u * 2 + 0) * 32]);
            u64t w1 = splat2(wv[(u * 2 + 1) * 32]);
            fma2(b0p[0], x0.x, w0); fma2(b0p[1], x0.y, w0);
            fma2(b0p[2], x1.x, w0); fma2(b0p[3], x1.y, w0);
            fma2(b1p[0], x0.x, w1); fma2(b1p[1], x0.y, w1);
            fma2(b1p[2], x1.x, w1); fma2(b1p[3], x1.y, w1);
        }
        float B0[8], B1[8];
        #pragma unroll
        for (int k2 = 0; k2 < 4; k2++) {
            float2 f = unpack2(b0p[k2]); B0[2 * k2] = f.x; B0[2 * k2 + 1] = f.y;
            float2 g = unpack2(b1p[k2]); B1[2 * k2] = g.x; B1[2 * k2 + 1] = g.y;
        }
        #pragma unroll
        for (int j = 0; j < 8; j++) {
            const float* xv = s_x2v + (e8 + j) * 97 + v0 * 3;
            vA[j][0] += B0[j] * xv[0] + B1[j] * xv[3];
            vA[j][1] += B0[j] * xv[1] + B1[j] * xv[4];
            vA[j][2] += B0[j] * xv[2] + B1[j] * xv[5];
        }
    }

    // vs:  B2[e,u,w] = sum_v x2s[e,v]*wvsv[u,v,w];  vec += B2 * x1v[e,u,i]
    for (int uc = 0; uc < 16; uc++) {
        __syncthreads();
        #pragma unroll
        for (int i = 0; i < 8; i++) {
            int idx = tid + NT * i; int r = idx >> 3, c4 = idx & 7;
            *(float4*)(s_un + r * 32 + c4 * 4) = vreg[i];
        }
        if (uc + 1 < 16) {
            int u0 = (uc + 1) * 2;
            #pragma unroll
            for (int i = 0; i < 8; i++) {
                int idx = tid + NT * i; int r = idx >> 3, c4 = idx & 7;
                vreg[i] = *(const float4*)(wvsv + (u0 + (r >> 6)) * 2048 + (r & 63) * 32 + c4 * 4);
            }
        }
        __syncthreads();

        int u0 = uc * 2;
        u64t b0p[4] = {0ull, 0ull, 0ull, 0ull};
        u64t b1p[4] = {0ull, 0ull, 0ull, 0ull};
        const float* wv = s_un + lane;
        #pragma unroll 8
        for (int v = 0; v < 64; v++) {
            ulonglong2 x0 = *(const ulonglong2*)(s_x2sT + v * 36 + e8);
            ulonglong2 x1 = *(const ulonglong2*)(s_x2sT + v * 36 + e8 + 4);
            u64t w0 = splat2(wv[v * 32]);
            u64t w1 = splat2(wv[(64 + v) * 32]);
            fma2(b0p[0], x0.x, w0); fma2(b0p[1], x0.y, w0);
            fma2(b0p[2], x1.x, w0); fma2(b0p[3], x1.y, w0);
            fma2(b1p[0], x0.x, w1); fma2(b1p[1], x0.y, w1);
            fma2(b1p[2], x1.x, w1); fma2(b1p[3], x1.y, w1);
        }
        float B0[8], B1[8];
        #pragma unroll
        for (int k2 = 0; k2 < 4; k2++) {
            float2 f = unpack2(b0p[k2]); B0[2 * k2] = f.x; B0[2 * k2 + 1] = f.y;
            float2 g = unpack2(b1p[k2]); B1[2 * k2] = g.x; B1[2 * k2 + 1] = g.y;
        }
        #pragma unroll
        for (int j = 0; j < 8; j++) {
            const float* xv = s_x1v + (e8 + j) * 97 + u0 * 3;
            vA[j][0] += B0[j] * xv[0] + B1[j] * xv[3];
            vA[j][1] += B0[j] * xv[1] + B1[j] * xv[4];
            vA[j][2] += B0[j] * xv[2] + B1[j] * xv[5];
        }
    }

    // ---- vec epilogue ----
    #pragma unroll
    for (int j = 0; j < 8; j++) {
        int e = e8 + j;
        float m = A_VEC_F * s_sig[e * 32 + lane] * s_wout[e * 96 + 64 + lane];
        float* o = out + (long)(e0g + e) * 160 + 64 + lane * 3;
        o[0] = vA[j][0] * m;
        o[1] = vA[j][1] * m;
        o[2] = vA[j][2] * m;
    }
}

extern "C" void kernel_launch(void* const* d_in, const int* in_sizes, int n_in,
                              void* d_out, int out_size) {
    (void)in_sizes; (void)n_in; (void)out_size;
    const float* fea_in1    = (const float*)d_in[0];
    const float* fea_in2    = (const float*)d_in[1];
    const float* fea_weight = (const float*)d_in[2];
    const float* w_ss_s     = (const float*)d_in[3];
    const float* w_vv_s     = (const float*)d_in[4];
    const float* w_ss_g     = (const float*)d_in[5];
    const float* w_vv_g     = (const float*)d_in[6];
    const float* w_sv_v     = (const float*)d_in[7];
    const float* w_vs_v     = (const float*)d_in[8];
    const float* fc_w1      = (const float*)d_in[9];
    const float* fc_b1      = (const float*)d_in[10];
    const float* fc_w2      = (const float*)d_in[11];
    const float* fc_b2      = (const float*)d_in[12];
    const float* fc_w3      = (const float*)d_in[13];
    const float* fc_b3      = (const float*)d_in[14];
    float* out = (float*)d_out;

    cudaFuncSetAttribute(equiconv_kernel,
                         cudaFuncAttributeMaxDynamicSharedMemorySize,
                         SMEM_FLOATS * sizeof(float));
    cudaFuncSetAttribute(equiconv_kernel,
                         cudaFuncAttributePreferredSharedMemoryCarveout,
                         cudaSharedmemCarveoutMaxShared);

    const int E = 20000;
    dim3 grid(E / TE);
    dim3 block(NT);
    equiconv_kernel<<<grid, block, SMEM_FLOATS * sizeof(float)>>>(
        fea_in1, fea_in2, fea_weight,
        w_ss_s, w_vv_s, w_ss_g, w_vv_g, w_sv_v, w_vs_v,
        fc_w1, fc_b1, fc_w2, fc_b2, fc_w3, fc_b3,
        out);
}